// round 13
// baseline (speedup 1.0000x reference)
#include <cuda_runtime.h>
#include <cuda_fp16.h>
#include <cstdint>

#define BB      2048
#define NN      64
#define DD      256
#define NSTEPS  4
#define XSH     264            // xs_h row stride in halfs (528B)

// Light kernel (nk 4..6): 512 thr, MTILE 64, 2 CTAs/SM, W resident
#define L_MTILE   64
#define L_THREADS 512
#define L_XSH_B   (L_MTILE * XSH * 2)        // 33792
#define L_BIAS    L_XSH_B
#define L_WOFF    (L_BIAS + 1024)            // 34816
#define L_SMEM    (L_WOFF + 73728)           // 108544 (2 CTAs/SM)

// Heavy kernel (nk 7..8): 1024 thr, MTILE 128, 1 CTA/SM, W resident
#define H_MTILE   128
#define H_THREADS 1024
#define H_XSH_B   (H_MTILE * XSH * 2)        // 67584
#define H_BIAS    H_XSH_B
#define H_WOFF    (H_BIAS + 1024)            // 68608
#define H_SMEM    (H_WOFF + 131072)          // 199680 (1 CTA/SM)

// Scratch (device globals)
// g_wpack[n][kc32][t][lane] (uint4): masked W fp16, m16n8k16 B-frag order.
//   j = t*8 + (lane>>2); i0 = kc32*32 + 2*(lane&3);
//   .x=(i0,i0+1) .y=(+8,+9) [sub0];  .z=(+16,+17) .w=(+24,+25) [sub1]
// Granule stride: 1024 uint4 (32 tiles always); active tiles t < 4*NT contiguous.
__device__ __align__(16) uint4 g_wpack[NN * 8 * 32 * 32];
__device__ float g_b[NN * DD];
__device__ int   g_nact[NN];

// ---------------------------------------------------------------------------
// PTX helpers (plain sm_80+ PTX)
// ---------------------------------------------------------------------------
__device__ __forceinline__ void mma16816(float* d, const uint32_t* a,
                                         uint32_t b0, uint32_t b1) {
    asm volatile(
        "mma.sync.aligned.m16n8k16.row.col.f32.f16.f16.f32 "
        "{%0,%1,%2,%3}, {%4,%5,%6,%7}, {%8,%9}, {%0,%1,%2,%3};"
        : "+f"(d[0]), "+f"(d[1]), "+f"(d[2]), "+f"(d[3])
        : "r"(a[0]), "r"(a[1]), "r"(a[2]), "r"(a[3]), "r"(b0), "r"(b1));
}
__device__ __forceinline__ void ldmatrix4(uint32_t* a, uint32_t addr) {
    asm volatile("ldmatrix.sync.aligned.m8n8.x4.shared.b16 {%0,%1,%2,%3}, [%4];"
                 : "=r"(a[0]), "=r"(a[1]), "=r"(a[2]), "=r"(a[3]) : "r"(addr));
}
__device__ __forceinline__ void cp16(uint32_t s_dst, const void* g_src) {
    asm volatile("cp.async.cg.shared.global [%0], [%1], 16;"
                 :: "r"(s_dst), "l"(g_src) : "memory");
}
__device__ __forceinline__ void cp_commit() {
    asm volatile("cp.async.commit_group;" ::: "memory");
}
__device__ __forceinline__ void cp_wait0() {
    asm volatile("cp.async.wait_group 0;" ::: "memory");
}
__device__ __forceinline__ uint32_t h2u(__half2 h) { return *(uint32_t*)&h; }

// ---------------------------------------------------------------------------
// Prep: premask W -> fp16 uint4 B-fragments; blocks >= 2048 do bias + nact
// ---------------------------------------------------------------------------
__global__ void prep_kernel(const float* __restrict__ w,
                            const float* __restrict__ wm,
                            const float* __restrict__ b,
                            const float* __restrict__ bm) {
    if (blockIdx.x >= 2048) {
        const int n = blockIdx.x - 2048, t = threadIdx.x;
        __shared__ int cnt;
        if (t == 0) cnt = 0;
        __syncthreads();
        float m = bm[n * DD + t];
        g_b[n * DD + t] = b[n * DD + t] * m;
        if (m != 0.f) atomicAdd(&cnt, 1);
        __syncthreads();
        if (t == 0) g_nact[n] = cnt;
        return;
    }
    int q = blockIdx.x * 256 + threadIdx.x;          // [0, 64*8*32*32)
    int lane = q & 31, t = (q >> 5) & 31, kc = (q >> 10) & 7, n = q >> 13;
    int j = t * 8 + (lane >> 2);
    int i0 = kc * 32 + 2 * (lane & 3);
    size_t base = ((size_t)n * DD + j) * DD + i0;
    uint4 r;
    {
        float2 v = *(const float2*)(w + base), m = *(const float2*)(wm + base);
        r.x = h2u(__floats2half2_rn(v.x * m.x, v.y * m.y));
    }
    {
        float2 v = *(const float2*)(w + base + 8), m = *(const float2*)(wm + base + 8);
        r.y = h2u(__floats2half2_rn(v.x * m.x, v.y * m.y));
    }
    {
        float2 v = *(const float2*)(w + base + 16), m = *(const float2*)(wm + base + 16);
        r.z = h2u(__floats2half2_rn(v.x * m.x, v.y * m.y));
    }
    {
        float2 v = *(const float2*)(w + base + 24), m = *(const float2*)(wm + base + 24);
        r.w = h2u(__floats2half2_rn(v.x * m.x, v.y * m.y));
    }
    g_wpack[q] = r;
}

extern __shared__ __align__(16) unsigned char smem_raw[];

// ---------------------------------------------------------------------------
// Shared hot-loop body (parametrized on geometry). Warp (mi, ni); warp owns
// xs rows [mi*16, mi*16+16) exclusively. W fully resident in SMEM.
// ---------------------------------------------------------------------------
template <int NT, int NTHREADS, int MWARPS, int WOFF>
__device__ __forceinline__ void steps_resident(__half* xsh, const float* bsm,
                                               const uint4* wsrc,
                                               int tid, int wid, int lane) {
    uint4* wbuf = (uint4*)(smem_raw + WOFF);
    const uint32_t smem_u = (uint32_t)__cvta_generic_to_shared(smem_raw);
    const uint32_t wb_u = smem_u + WOFF;

    // Load ALL active W once: NT granules x (128*NT contiguous uint4 each)
    {
        const int per_g = 128 * NT;
        for (int v = tid; v < NT * per_g; v += NTHREADS) {
            int g = v / per_g, within = v - g * per_g;
            cp16(wb_u + v * 16, wsrc + g * 1024 + within);
        }
        cp_commit(); cp_wait0();
    }
    __syncthreads();           // x tile + bias + W all visible

    const int mi = wid & (MWARPS - 1), ni = wid / MWARPS;
    const int row_l = (lane & 15);
    const int koff = (lane >> 4) * 8;
    const uint32_t abase = smem_u + ((mi * 16 + row_l) * XSH + koff) * 2;

    const int rE = mi * 16 + (lane >> 2);
    const int cq = 2 * (lane & 3);
    const int nbase = ni * NT * 8;

    float acc[NT][4];

    for (int step = 0; step < NSTEPS; ++step) {
#pragma unroll
        for (int t = 0; t < NT; ++t)
#pragma unroll
            for (int q = 0; q < 4; ++q) acc[t][q] = 0.f;

#pragma unroll
        for (int s = 0; s < NT; ++s) {
            uint32_t a[2][4];
            const int kbyte = s * 64;
            ldmatrix4(a[0], abase + kbyte);
            ldmatrix4(a[1], abase + kbyte + 32);

            const uint4* bp = wbuf + s * (128 * NT) + ni * NT * 32 + lane;
#pragma unroll
            for (int t = 0; t < NT; ++t) {
                uint4 bfr = bp[t * 32];
                mma16816(acc[t], a[0], bfr.x, bfr.y);
                mma16816(acc[t], a[1], bfr.z, bfr.w);
            }
        }

        __syncthreads();   // all A reads done before epilogue writes xs

#pragma unroll
        for (int t = 0; t < NT; ++t) {
            const int c = nbase + t * 8 + cq;
            float2 bv = *(const float2*)&bsm[c];
            {
                __half2* p = (__half2*)&xsh[rE * XSH + c];
                float2 fx = __half22float2(*p);
                fx.x += fmaxf(acc[t][0] + bv.x, 0.f);
                fx.y += fmaxf(acc[t][1] + bv.y, 0.f);
                *p = __floats2half2_rn(fx.x, fx.y);
            }
            {
                __half2* p = (__half2*)&xsh[(rE + 8) * XSH + c];
                float2 fx = __half22float2(*p);
                fx.x += fmaxf(acc[t][2] + bv.x, 0.f);
                fx.y += fmaxf(acc[t][3] + bv.y, 0.f);
                *p = __floats2half2_rn(fx.x, fx.y);
            }
        }

        __syncthreads();   // epilogue visible before next step's reads
    }
}

// Generic tile load / store
template <int MT, int NTHREADS>
__device__ __forceinline__ void load_x(__half* xsh, const float* x_in,
                                       int n, int r0, int tid) {
    const float4* xin4 = (const float4*)x_in;
    for (int v = tid; v < MT * 64; v += NTHREADS) {
        int row = v >> 6, c4 = v & 63;
        float4 f = xin4[((size_t)(r0 + row) * NN + n) * 64 + c4];
        uint2 h;
        h.x = h2u(__floats2half2_rn(f.x, f.y));
        h.y = h2u(__floats2half2_rn(f.z, f.w));
        *(uint2*)&xsh[row * XSH + c4 * 4] = h;
    }
}

template <int MT, int NTHREADS>
__device__ __forceinline__ void store_x(const __half* xsh, const float* x_in,
                                        float* x_out, int n, int r0,
                                        int nact, int tid) {
    const float4* xin4 = (const float4*)x_in;
    float4* xo = (float4*)x_out;
    for (int v = tid; v < MT * 64; v += NTHREADS) {
        int row = v >> 6, c4 = v & 63;
        size_t gi = ((size_t)(r0 + row) * NN + n) * 64 + c4;
        float4 f;
        if (c4 * 4 < nact) {
            uint2 h = *(const uint2*)&xsh[row * XSH + c4 * 4];
            float2 lo = __half22float2(*(__half2*)&h.x);
            float2 hi = __half22float2(*(__half2*)&h.y);
            f.x = lo.x; f.y = lo.y; f.z = hi.x; f.w = hi.y;
        } else {
            f = xin4[gi];
        }
        xo[gi] = f;
    }
}

// ---------------------------------------------------------------------------
// HEAVY kernel: nk in {7, 8}. 1024 thr, MTILE=128, 8M x 4N, 1 CTA/SM.
// rank r < 12 -> n = 4 + 5r (nk=8); else n = 3 + 5(r-12) (nk=7).
// ---------------------------------------------------------------------------
__global__ __launch_bounds__(H_THREADS, 1)
void blm_heavy_kernel(const float* __restrict__ x_in, float* __restrict__ x_out) {
    const int rank = blockIdx.x >> 4;               // 25 groups x 16 tiles
    const bool is8 = (rank < 12);
    const int n = is8 ? (4 + 5 * rank) : (3 + 5 * (rank - 12));
    const int r0 = (blockIdx.x & 15) * H_MTILE;
    const int nact = is8 ? 256 : 224;

    __half* xsh = (__half*)smem_raw;
    float* bsm = (float*)(smem_raw + H_BIAS);
    const int tid = threadIdx.x;
    const int wid = tid >> 5, lane = tid & 31;

    if (tid < DD) bsm[tid] = g_b[n * DD + tid];
    load_x<H_MTILE, H_THREADS>(xsh, x_in, n, r0, tid);
    // steps_resident begins with __syncthreads() covering xs/bias/W visibility

    const uint4* wsrc = g_wpack + ((size_t)n << 13);
    if (is8) steps_resident<8, H_THREADS, 8, H_WOFF>(xsh, bsm, wsrc, tid, wid, lane);
    else     steps_resident<7, H_THREADS, 8, H_WOFF>(xsh, bsm, wsrc, tid, wid, lane);

    __syncthreads();
    store_x<H_MTILE, H_THREADS>(xsh, x_in, x_out, n, r0, nact, tid);
}

// ---------------------------------------------------------------------------
// LIGHT kernel: nk in {4, 5, 6}. 512 thr, MTILE=64, 4M x 4N, 2 CTAs/SM.
// rank r < 13 -> n = 2 + 5r (nk=6); r < 26 -> n = 1 + 5(r-13) (nk=5);
// else n = 5(r-26) (nk=4).
// ---------------------------------------------------------------------------
__global__ __launch_bounds__(L_THREADS, 2)
void blm_light_kernel(const float* __restrict__ x_in, float* __restrict__ x_out) {
    const int rank = blockIdx.x >> 5;               // 39 groups x 32 tiles
    int n, nk;
    if (rank < 13)      { n = 2 + 5 * rank;        nk = 6; }
    else if (rank < 26) { n = 1 + 5 * (rank - 13); nk = 5; }
    else                { n = 5 * (rank - 26);     nk = 4; }
    const int r0 = (blockIdx.x & 31) * L_MTILE;
    const int nact = nk * 32;

    __half* xsh = (__half*)smem_raw;
    float* bsm = (float*)(smem_raw + L_BIAS);
    const int tid = threadIdx.x;
    const int wid = tid >> 5, lane = tid & 31;

    if (tid < DD) bsm[tid] = g_b[n * DD + tid];
    load_x<L_MTILE, L_THREADS>(xsh, x_in, n, r0, tid);

    const uint4* wsrc = g_wpack + ((size_t)n << 13);
    switch (nk) {
        case 6: steps_resident<6, L_THREADS, 4, L_WOFF>(xsh, bsm, wsrc, tid, wid, lane); break;
        case 5: steps_resident<5, L_THREADS, 4, L_WOFF>(xsh, bsm, wsrc, tid, wid, lane); break;
        default: steps_resident<4, L_THREADS, 4, L_WOFF>(xsh, bsm, wsrc, tid, wid, lane); break;
    }

    __syncthreads();
    store_x<L_MTILE, L_THREADS>(xsh, x_in, x_out, n, r0, nact, tid);
}

// ---------------------------------------------------------------------------
// Launch: heavy first (1 CTA/SM), light fills its tail (2 CTAs/SM).
// ---------------------------------------------------------------------------
extern "C" void kernel_launch(void* const* d_in, const int* in_sizes, int n_in,
                              void* d_out, int out_size) {
    const float* x  = (const float*)d_in[0];
    const float* w  = (const float*)d_in[1];
    const float* b  = (const float*)d_in[2];
    const float* wm = (const float*)d_in[3];
    const float* bm = (const float*)d_in[4];
    float* out = (float*)d_out;

    cudaFuncSetAttribute(blm_heavy_kernel,
                         cudaFuncAttributeMaxDynamicSharedMemorySize, H_SMEM);
    cudaFuncSetAttribute(blm_light_kernel,
                         cudaFuncAttributeMaxDynamicSharedMemorySize, L_SMEM);

    prep_kernel<<<2048 + 64, 256>>>(w, wm, b, bm);
    blm_heavy_kernel<<<25 * (BB / H_MTILE), H_THREADS, H_SMEM>>>(x, out);
    blm_light_kernel<<<39 * (BB / L_MTILE), L_THREADS, L_SMEM>>>(x, out);
}

// round 15
// speedup vs baseline: 1.1256x; 1.1256x over previous
#include <cuda_runtime.h>
#include <cuda_fp16.h>
#include <cstdint>

#define BB      2048
#define NN      64
#define DD      256
#define NSTEPS  4
#define MTILE   64
#define THREADS 512            // 16 warps: 4 (M) x 4 (N)
#define XSH     264            // xs_h row stride in halfs (528B)

// SMEM layout (bytes)
#define XSH_B   (MTILE * XSH * 2)        // 33792
#define BIAS_O  XSH_B                    // 1024 B fp32
#define WOFF    (BIAS_O + 1024)          // 34816
#define SMEM_T  (WOFF + 73728)           // 108544 (2 CTAs/SM)

// Grid: heavy (nk 7,8) = 25 ranks x 32 tiles = 800; light = 39 ranks x 16 = 624
#define HEAVY_CTAS 800
#define TOTAL_CTAS 1424

// Scratch (device globals)
// g_wpack[n][kc32][t][lane] (uint4): masked W fp16, m16n8k16 B-frag order.
//   j = t*8 + (lane>>2); i0 = kc32*32 + 2*(lane&3);
//   .x=(i0,i0+1) .y=(+8,+9) [sub0];  .z=(+16,+17) .w=(+24,+25) [sub1]
// Granule stride 1024 uint4 (32 tiles always); active tiles t < 4*NT contiguous.
__device__ __align__(16) uint4 g_wpack[NN * 8 * 32 * 32];
__device__ float g_b[NN * DD];

// ---------------------------------------------------------------------------
// PTX helpers (plain sm_80+ PTX)
// ---------------------------------------------------------------------------
__device__ __forceinline__ void mma16816(float* d, const uint32_t* a,
                                         uint32_t b0, uint32_t b1) {
    asm volatile(
        "mma.sync.aligned.m16n8k16.row.col.f32.f16.f16.f32 "
        "{%0,%1,%2,%3}, {%4,%5,%6,%7}, {%8,%9}, {%0,%1,%2,%3};"
        : "+f"(d[0]), "+f"(d[1]), "+f"(d[2]), "+f"(d[3])
        : "r"(a[0]), "r"(a[1]), "r"(a[2]), "r"(a[3]), "r"(b0), "r"(b1));
}
__device__ __forceinline__ void ldmatrix4(uint32_t* a, uint32_t addr) {
    asm volatile("ldmatrix.sync.aligned.m8n8.x4.shared.b16 {%0,%1,%2,%3}, [%4];"
                 : "=r"(a[0]), "=r"(a[1]), "=r"(a[2]), "=r"(a[3]) : "r"(addr));
}
__device__ __forceinline__ void cp16(uint32_t s_dst, const void* g_src) {
    asm volatile("cp.async.cg.shared.global [%0], [%1], 16;"
                 :: "r"(s_dst), "l"(g_src) : "memory");
}
__device__ __forceinline__ void cp_commit() {
    asm volatile("cp.async.commit_group;" ::: "memory");
}
__device__ __forceinline__ void cp_wait0() {
    asm volatile("cp.async.wait_group 0;" ::: "memory");
}
__device__ __forceinline__ uint32_t h2u(__half2 h) { return *(uint32_t*)&h; }

// ---------------------------------------------------------------------------
// Prep: premask W -> fp16 uint4 B-fragments; blocks >= 2048 mask bias
// ---------------------------------------------------------------------------
__global__ void prep_kernel(const float* __restrict__ w,
                            const float* __restrict__ wm,
                            const float* __restrict__ b,
                            const float* __restrict__ bm) {
    if (blockIdx.x >= 2048) {
        const int n = blockIdx.x - 2048, t = threadIdx.x;
        g_b[n * DD + t] = b[n * DD + t] * bm[n * DD + t];
        return;
    }
    int q = blockIdx.x * 256 + threadIdx.x;          // [0, 64*8*32*32)
    int lane = q & 31, t = (q >> 5) & 31, kc = (q >> 10) & 7, n = q >> 13;
    int j = t * 8 + (lane >> 2);
    int i0 = kc * 32 + 2 * (lane & 3);
    size_t base = ((size_t)n * DD + j) * DD + i0;
    uint4 r;
    {
        float2 v = *(const float2*)(w + base), m = *(const float2*)(wm + base);
        r.x = h2u(__floats2half2_rn(v.x * m.x, v.y * m.y));
    }
    {
        float2 v = *(const float2*)(w + base + 8), m = *(const float2*)(wm + base + 8);
        r.y = h2u(__floats2half2_rn(v.x * m.x, v.y * m.y));
    }
    {
        float2 v = *(const float2*)(w + base + 16), m = *(const float2*)(wm + base + 16);
        r.z = h2u(__floats2half2_rn(v.x * m.x, v.y * m.y));
    }
    {
        float2 v = *(const float2*)(w + base + 24), m = *(const float2*)(wm + base + 24);
        r.w = h2u(__floats2half2_rn(v.x * m.x, v.y * m.y));
    }
    g_wpack[q] = r;
}

extern __shared__ __align__(16) unsigned char smem_raw[];

// ---------------------------------------------------------------------------
// Building blocks
// ---------------------------------------------------------------------------
template <int NT>
__device__ __forceinline__ void issue_w_resident(uint32_t wb_u, const uint4* wsrc,
                                                 int tid) {
    const int per_g = 128 * NT;
    for (int v = tid; v < NT * per_g; v += THREADS) {
        int g = v / per_g, wi = v - g * per_g;
        cp16(wb_u + v * 16, wsrc + g * 1024 + wi);
    }
    cp_commit();
}

template <int NT>
__device__ __forceinline__ void issue_stage(uint32_t dst, const uint4* wsrc,
                                            int st, int tid) {
    const int GR = 128 * NT;
    const int g0 = 2 * st;
    const int ng = (g0 + 1 < NT) ? 2 : 1;
    for (int v = tid; v < ng * GR; v += THREADS) {
        int g = v / GR, wi = v - g * GR;
        cp16(dst + v * 16, wsrc + (g0 + g) * 1024 + wi);
    }
    cp_commit();
}

// One k32 granule of MMAs for this warp: A via 2 ldmatrix.x4, B one LDS.128/tile.
template <int NT>
__device__ __forceinline__ void granule_mma(float (*acc)[4], const uint4* bb,
                                            uint32_t abase, int s, int niNT,
                                            int lane) {
    uint32_t a[2][4];
    ldmatrix4(a[0], abase + s * 64);
    ldmatrix4(a[1], abase + s * 64 + 32);
    const uint4* bp = bb + niNT * 32 + lane;
#pragma unroll
    for (int t = 0; t < NT; ++t) {
        uint4 b = bp[t * 32];
        mma16816(acc[t], a[0], b.x, b.y);
        mma16816(acc[t], a[1], b.z, b.w);
    }
}

template <int NT>
__device__ __forceinline__ void epilogue(float (*acc)[4], __half* xsh,
                                         const float* bsm, int rE, int cq,
                                         int nbase) {
#pragma unroll
    for (int t = 0; t < NT; ++t) {
        const int c = nbase + t * 8 + cq;
        float2 bv = *(const float2*)&bsm[c];
        {
            __half2* p = (__half2*)&xsh[rE * XSH + c];
            float2 fx = __half22float2(*p);
            fx.x += fmaxf(acc[t][0] + bv.x, 0.f);
            fx.y += fmaxf(acc[t][1] + bv.y, 0.f);
            *p = __floats2half2_rn(fx.x, fx.y);
        }
        {
            __half2* p = (__half2*)&xsh[(rE + 8) * XSH + c];
            float2 fx = __half22float2(*p);
            fx.x += fmaxf(acc[t][2] + bv.x, 0.f);
            fx.y += fmaxf(acc[t][3] + bv.y, 0.f);
            *p = __floats2half2_rn(fx.x, fx.y);
        }
    }
}

__device__ __forceinline__ void load_x(__half* xsh, const float* x_in,
                                       int n, int r0, int tid) {
    const float4* xin4 = (const float4*)x_in;
    for (int v = tid; v < MTILE * 64; v += THREADS) {
        int row = v >> 6, c4 = v & 63;
        float4 f = xin4[((size_t)(r0 + row) * NN + n) * 64 + c4];
        uint2 h;
        h.x = h2u(__floats2half2_rn(f.x, f.y));
        h.y = h2u(__floats2half2_rn(f.z, f.w));
        *(uint2*)&xsh[row * XSH + c4 * 4] = h;
    }
}

__device__ __forceinline__ void store_x(const __half* xsh, const float* x_in,
                                        float* x_out, int n, int r0, int nact,
                                        int tid) {
    const float4* xin4 = (const float4*)x_in;
    float4* xo = (float4*)x_out;
    for (int v = tid; v < MTILE * 64; v += THREADS) {
        int row = v >> 6, c4 = v & 63;
        size_t gi = ((size_t)(r0 + row) * NN + n) * 64 + c4;
        float4 f;
        if (c4 * 4 < nact) {
            uint2 h = *(const uint2*)&xsh[row * XSH + c4 * 4];
            float2 lo = __half22float2(*(__half2*)&h.x);
            float2 hi = __half22float2(*(__half2*)&h.y);
            f.x = lo.x; f.y = lo.y; f.z = hi.x; f.w = hi.y;
        } else {
            f = xin4[gi];
        }
        xo[gi] = f;
    }
}

// ---------------------------------------------------------------------------
// Resident-W 4-step run (nk 4..6). Caller issued W + loaded x; we wait+sync.
// ---------------------------------------------------------------------------
template <int NT>
__device__ __forceinline__ void run_resident(__half* xsh, const float* bsm,
                                             int tid, int wid, int lane) {
    uint4* wbuf = (uint4*)(smem_raw + WOFF);
    const uint32_t smem_u = (uint32_t)__cvta_generic_to_shared(smem_raw);
    const int GR = 128 * NT;

    cp_wait0();
    __syncthreads();           // x tile + bias + W all visible

    const int mi = wid & 3, ni = wid >> 2;
    const uint32_t abase =
        smem_u + ((mi * 16 + (lane & 15)) * XSH + (lane >> 4) * 8) * 2;
    const int rE = mi * 16 + (lane >> 2);
    const int cq = 2 * (lane & 3);
    const int nbase = ni * NT * 8;

    float acc[NT][4];
    for (int step = 0; step < NSTEPS; ++step) {
#pragma unroll
        for (int t = 0; t < NT; ++t)
#pragma unroll
            for (int q = 0; q < 4; ++q) acc[t][q] = 0.f;

#pragma unroll
        for (int s = 0; s < NT; ++s)
            granule_mma<NT>(acc, wbuf + s * GR, abase, s, ni * NT, lane);

        __syncthreads();       // all A reads done before epilogue writes
        epilogue<NT>(acc, xsh, bsm, rE, cq, nbase);
        __syncthreads();       // epilogue visible before next step / store
    }
}

// ---------------------------------------------------------------------------
// Streaming-W 4-step run (nk 7..8). 2-granule stages, ring of 2, cross-step
// stage-0 prefetch. Caller issued stage 0 + loaded x; we wait+sync.
// ---------------------------------------------------------------------------
template <int NT>
__device__ __forceinline__ void run_stream(__half* xsh, const float* bsm,
                                           const uint4* wsrc,
                                           int tid, int wid, int lane) {
    const int GR = 128 * NT;
    const int NSg = (NT + 1) / 2;     // 4 for NT=7,8
    const int STGU4 = 2 * GR;         // stage buffer stride (uint4)
    uint4* wbuf = (uint4*)(smem_raw + WOFF);
    const uint32_t smem_u = (uint32_t)__cvta_generic_to_shared(smem_raw);
    const uint32_t wb_u = smem_u + WOFF;

    cp_wait0();
    __syncthreads();           // x tile + bias + stage 0 visible

    const int mi = wid & 3, ni = wid >> 2;
    const uint32_t abase =
        smem_u + ((mi * 16 + (lane & 15)) * XSH + (lane >> 4) * 8) * 2;
    const int rE = mi * 16 + (lane >> 2);
    const int cq = 2 * (lane & 3);
    const int nbase = ni * NT * 8;

    int buf = 0;
    float acc[NT][4];
    for (int step = 0; step < NSTEPS; ++step) {
#pragma unroll
        for (int t = 0; t < NT; ++t)
#pragma unroll
            for (int q = 0; q < 4; ++q) acc[t][q] = 0.f;

#pragma unroll
        for (int st = 0; st < NSg; ++st) {
            const bool last_all = (step == NSTEPS - 1) && (st == NSg - 1);
            if (!last_all) {
                // next stage (wraps to stage 0 of the next step; W is
                // step-invariant so the source is just the stage index)
                const int nxt = (st + 1 < NSg) ? st + 1 : 0;
                issue_stage<NT>(wb_u + (buf ^ 1) * (STGU4 * 16), wsrc, nxt, tid);
            }
            const uint4* bb = wbuf + buf * STGU4;
            granule_mma<NT>(acc, bb, abase, 2 * st, ni * NT, lane);
            if (2 * st + 1 < NT)
                granule_mma<NT>(acc, bb + GR, abase, 2 * st + 1, ni * NT, lane);

            if (!last_all) cp_wait0();
            __syncthreads();   // stage consumed; next stage data visible
            buf ^= 1;
        }
        // last stage's sync doubles as the pre-epilogue sync
        epilogue<NT>(acc, xsh, bsm, rE, cq, nbase);
        __syncthreads();       // epilogue visible before next step / store
    }
}

// ---------------------------------------------------------------------------
// Light body: resident W, TWO batch tiles sequentially per CTA
// ---------------------------------------------------------------------------
template <int NT>
__device__ __forceinline__ void light_body(const float* x_in, float* x_out,
                                           __half* xsh, float* bsm,
                                           const uint4* wsrc, int n, int bt2,
                                           int tid, int wid, int lane) {
    const uint32_t wb_u =
        (uint32_t)__cvta_generic_to_shared(smem_raw) + WOFF;
    issue_w_resident<NT>(wb_u, wsrc, tid);   // overlaps the x load below
#pragma unroll
    for (int tt = 0; tt < 2; ++tt) {
        const int r0 = (2 * bt2 + tt) * MTILE;
        load_x(xsh, x_in, n, r0, tid);
        run_resident<NT>(xsh, bsm, tid, wid, lane);
        store_x(xsh, x_in, x_out, n, r0, NT * 32, tid);
        __syncthreads();       // store done before next tile's load overwrites xs
    }
}

// ---------------------------------------------------------------------------
// Unified kernel: heavy CTAs first (bid < 800), then light double-tile CTAs
// ---------------------------------------------------------------------------
__global__ __launch_bounds__(THREADS, 2)
void blm_all_kernel(const float* __restrict__ x_in, float* __restrict__ x_out) {
    __half* xsh = (__half*)smem_raw;
    float* bsm = (float*)(smem_raw + BIAS_O);
    const int tid = threadIdx.x;
    const int wid = tid >> 5, lane = tid & 31;
    const int bid = blockIdx.x;
    const uint32_t wb_u =
        (uint32_t)__cvta_generic_to_shared(smem_raw) + WOFF;

    if (bid < HEAVY_CTAS) {
        const int rank = bid >> 5, bt = bid & 31;
        const bool is8 = (rank < 12);
        const int n = is8 ? (4 + 5 * rank) : (3 + 5 * (rank - 12));
        const int nact = is8 ? 256 : 224;
        const uint4* wsrc = g_wpack + ((size_t)n << 13);

        if (tid < DD) bsm[tid] = g_b[n * DD + tid];
        if (is8) issue_stage<8>(wb_u, wsrc, 0, tid);
        else     issue_stage<7>(wb_u, wsrc, 0, tid);
        load_x(xsh, x_in, n, bt * MTILE, tid);

        if (is8) run_stream<8>(xsh, bsm, wsrc, tid, wid, lane);
        else     run_stream<7>(xsh, bsm, wsrc, tid, wid, lane);

        store_x(xsh, x_in, x_out, n, bt * MTILE, nact, tid);
    } else {
        const int idx = bid - HEAVY_CTAS;
        const int rank = idx >> 4, bt2 = idx & 15;
        int n, nk;
        if (rank < 13)      { n = 2 + 5 * rank;        nk = 6; }
        else if (rank < 26) { n = 1 + 5 * (rank - 13); nk = 5; }
        else                { n = 5 * (rank - 26);     nk = 4; }
        const uint4* wsrc = g_wpack + ((size_t)n << 13);

        if (tid < DD) bsm[tid] = g_b[n * DD + tid];
        switch (nk) {
            case 6: light_body<6>(x_in, x_out, xsh, bsm, wsrc, n, bt2, tid, wid, lane); break;
            case 5: light_body<5>(x_in, x_out, xsh, bsm, wsrc, n, bt2, tid, wid, lane); break;
            default: light_body<4>(x_in, x_out, xsh, bsm, wsrc, n, bt2, tid, wid, lane); break;
        }
    }
}

// ---------------------------------------------------------------------------
// Launch
// ---------------------------------------------------------------------------
extern "C" void kernel_launch(void* const* d_in, const int* in_sizes, int n_in,
                              void* d_out, int out_size) {
    const float* x  = (const float*)d_in[0];
    const float* w  = (const float*)d_in[1];
    const float* b  = (const float*)d_in[2];
    const float* wm = (const float*)d_in[3];
    const float* bm = (const float*)d_in[4];
    float* out = (float*)d_out;

    cudaFuncSetAttribute(blm_all_kernel,
                         cudaFuncAttributeMaxDynamicSharedMemorySize, SMEM_T);

    prep_kernel<<<2048 + 64, 256>>>(w, wm, b, bm);
    blm_all_kernel<<<TOTAL_CTAS, THREADS, SMEM_T>>>(x, out);
}